// round 3
// baseline (speedup 1.0000x reference)
#include <cuda_runtime.h>

// EdgeDecoder: out[e] = sigmoid( relu([src_e ; dst_e] @ W1 + b1) @ W2 + b2 )
// Inputs (metadata order): node_embs_src f32[100000*128], node_embs_dst f32[100000*128],
//   edge_index int32[2*600000]  (JAX x64 disabled -> int32!), W1 f32[256*128],
//   b1 f32[128], W2 f32[128], b2 f32[1]
// Output: f32[600000]

#define D        128
#define K2       256            // 2*D
#define TILE_E   64             // edges per tile
#define NTHREADS 512            // 16 warps
#define XPAD     264            // padded row stride for X tile (16B-aligned, conflict-friendly)
#define GRID     148            // persistent blocks (one per SM)

__global__ __launch_bounds__(NTHREADS, 1)
void edge_decoder_kernel(const float* __restrict__ src_emb,
                         const float* __restrict__ dst_emb,
                         const int* __restrict__ eidx,
                         const float* __restrict__ W1,
                         const float* __restrict__ b1,
                         const float* __restrict__ W2,
                         const float* __restrict__ b2,
                         float* __restrict__ out,
                         int n_edges, int n_tiles)
{
    extern __shared__ float smem[];
    float* Ws = smem;                         // [256][128] = 32768 floats
    float* Xs = smem + K2 * D;                // [64][XPAD] = 16896 floats
    int*   sidx = (int*)(Xs + TILE_E * XPAD); // [64]
    int*   didx = sidx + TILE_E;              // [64]

    const int tid  = threadIdx.x;
    const int lane = tid & 31;
    const int warp = tid >> 5;                // 0..15

    // Stage W1 into shared memory once per block (coalesced float4).
    {
        const float4* w1v = (const float4*)W1;
        float4* wsv = (float4*)Ws;
        for (int i = tid; i < (K2 * D) / 4; i += NTHREADS)
            wsv[i] = w1v[i];
    }

    // Per-thread epilogue constants: this thread owns cols 4*lane..4*lane+3.
    float b1r[4], w2r[4];
    #pragma unroll
    for (int c = 0; c < 4; ++c) {
        b1r[c] = b1[4 * lane + c];
        w2r[c] = W2[4 * lane + c];
    }
    const float b2v = b2[0];

    __syncthreads();

    for (int tile = blockIdx.x; tile < n_tiles; tile += gridDim.x) {
        const int e0 = tile * TILE_E;

        // ---- load edge indices for this tile (int32 layout: row0 = src, row1 = dst) ----
        if (tid < TILE_E) {
            int e = e0 + tid;
            if (e < n_edges) {
                sidx[tid] = eidx[e];
                didx[tid] = eidx[n_edges + e];
            } else {
                sidx[tid] = 0;
                didx[tid] = 0;
            }
        }
        __syncthreads();

        // ---- gather X tile: 8 threads per edge, float4 rows ----
        {
            const int el = tid >> 3;          // 0..63
            const int g  = tid & 7;           // 0..7
            const float4* srow = (const float4*)(src_emb + (size_t)sidx[el] * D);
            const float4* drow = (const float4*)(dst_emb + (size_t)didx[el] * D);
            float4* xsrc = (float4*)(Xs + el * XPAD);
            float4* xdst = (float4*)(Xs + el * XPAD + D);
            #pragma unroll
            for (int i = 0; i < 4; ++i) {
                xsrc[g + 8 * i] = srow[g + 8 * i];
                xdst[g + 8 * i] = drow[g + 8 * i];
            }
        }
        __syncthreads();

        // ---- compute: warp -> edges 4*warp..+3, lane -> cols 4*lane..+3 ----
        float acc[4][4];
        #pragma unroll
        for (int e = 0; e < 4; ++e)
            #pragma unroll
            for (int c = 0; c < 4; ++c) acc[e][c] = 0.f;

        const float* xbase = Xs + (4 * warp) * XPAD;
        const float* wbase = Ws + 4 * lane;

        #pragma unroll 2
        for (int kb = 0; kb < K2 / 4; ++kb) {
            float xv[4][4];
            *(float4*)xv[0] = *(const float4*)(xbase + 0 * XPAD + kb * 4);
            *(float4*)xv[1] = *(const float4*)(xbase + 1 * XPAD + kb * 4);
            *(float4*)xv[2] = *(const float4*)(xbase + 2 * XPAD + kb * 4);
            *(float4*)xv[3] = *(const float4*)(xbase + 3 * XPAD + kb * 4);
            #pragma unroll
            for (int j = 0; j < 4; ++j) {
                float4 wv = *(const float4*)(wbase + (kb * 4 + j) * D);
                #pragma unroll
                for (int e = 0; e < 4; ++e) {
                    acc[e][0] = fmaf(xv[e][j], wv.x, acc[e][0]);
                    acc[e][1] = fmaf(xv[e][j], wv.y, acc[e][1]);
                    acc[e][2] = fmaf(xv[e][j], wv.z, acc[e][2]);
                    acc[e][3] = fmaf(xv[e][j], wv.w, acc[e][3]);
                }
            }
        }

        // ---- epilogue: relu + dot with W2 over this thread's 4 cols ----
        float p[4];
        #pragma unroll
        for (int e = 0; e < 4; ++e) {
            float s = 0.f;
            #pragma unroll
            for (int c = 0; c < 4; ++c) {
                float h = acc[e][c] + b1r[c];
                h = h > 0.f ? h : 0.f;
                s = fmaf(h, w2r[c], s);
            }
            p[e] = s;
        }
        // reduce across the 32 lanes (the 128 h-columns)
        #pragma unroll
        for (int off = 16; off > 0; off >>= 1) {
            #pragma unroll
            for (int e = 0; e < 4; ++e)
                p[e] += __shfl_xor_sync(0xffffffffu, p[e], off);
        }
        if (lane == 0) {
            int eg = e0 + 4 * warp;           // first of this warp's 4 edges
            if (eg + 3 < n_edges) {
                float4 o;
                o.x = 1.f / (1.f + expf(-(p[0] + b2v)));
                o.y = 1.f / (1.f + expf(-(p[1] + b2v)));
                o.z = 1.f / (1.f + expf(-(p[2] + b2v)));
                o.w = 1.f / (1.f + expf(-(p[3] + b2v)));
                *(float4*)(out + eg) = o;
            } else {
                for (int e = 0; e < 4 && eg + e < n_edges; ++e)
                    out[eg + e] = 1.f / (1.f + expf(-(p[e] + b2v)));
            }
        }

        __syncthreads();   // protect Xs/sidx before next tile's writes
    }
}

extern "C" void kernel_launch(void* const* d_in, const int* in_sizes, int n_in,
                              void* d_out, int out_size)
{
    const float* src = (const float*)d_in[0];
    const float* dst = (const float*)d_in[1];
    const int*   ei  = (const int*)d_in[2];
    const float* W1  = (const float*)d_in[3];
    const float* b1  = (const float*)d_in[4];
    const float* W2  = (const float*)d_in[5];
    const float* b2  = (const float*)d_in[6];
    float*       out = (float*)d_out;

    const int n_edges = in_sizes[2] / 2;
    const int n_tiles = (n_edges + TILE_E - 1) / TILE_E;

    const int smem_bytes = (K2 * D + TILE_E * XPAD) * (int)sizeof(float)
                         + 2 * TILE_E * (int)sizeof(int);
    cudaFuncSetAttribute(edge_decoder_kernel,
                         cudaFuncAttributeMaxDynamicSharedMemorySize, smem_bytes);

    int grid = GRID < n_tiles ? GRID : n_tiles;
    edge_decoder_kernel<<<grid, NTHREADS, smem_bytes>>>(
        src, dst, ei, W1, b1, W2, b2, out, n_edges, n_tiles);
}

// round 4
// speedup vs baseline: 2.3744x; 2.3744x over previous
#include <cuda_runtime.h>
#include <cuda_bf16.h>
#include <cstdint>

// EdgeDecoder: out[e] = sigmoid( relu([src_e ; dst_e] @ W1 + b1) @ W2 + b2 )
// Tensor-core version: fp32 -> bf16 hi/lo split, 3x mma.sync.m16n8k16, fp32 accum.
// Inputs: src f32[100000*128], dst f32[100000*128], edge_index i32[2*600000],
//         W1 f32[256*128], b1 f32[128], W2 f32[128], b2 f32[1]. Output f32[600000].

#define D        128
#define K2       256
#define TILE_E   64
#define NTHREADS 512            // 16 warps: 4 warp-rows (16 edges) x 4 warp-cols (32 cols)
#define XS       264            // bf16 row stride (256 + 8 pad) -> conflict-free frag loads
#define WS       264
#define GRID     148

__device__ __forceinline__ uint32_t lds32(const __nv_bfloat16* p) {
    return *(const uint32_t*)p;
}

__device__ __forceinline__ void mma16816(float c[4], uint32_t a0, uint32_t a1,
                                         uint32_t a2, uint32_t a3,
                                         uint32_t b0, uint32_t b1) {
    asm volatile(
        "mma.sync.aligned.m16n8k16.row.col.f32.bf16.bf16.f32 "
        "{%0,%1,%2,%3}, {%4,%5,%6,%7}, {%8,%9}, {%0,%1,%2,%3};\n"
        : "+f"(c[0]), "+f"(c[1]), "+f"(c[2]), "+f"(c[3])
        : "r"(a0), "r"(a1), "r"(a2), "r"(a3), "r"(b0), "r"(b1));
}

__global__ __launch_bounds__(NTHREADS, 1)
void edge_decoder_tc(const float* __restrict__ src_emb,
                     const float* __restrict__ dst_emb,
                     const int* __restrict__ eidx,
                     const float* __restrict__ W1,
                     const float* __restrict__ b1,
                     const float* __restrict__ W2,
                     const float* __restrict__ b2,
                     float* __restrict__ out,
                     int n_edges, int n_tiles)
{
    extern __shared__ char smem[];
    __nv_bfloat16* sWhi = (__nv_bfloat16*)smem;          // [128 n][WS k]
    __nv_bfloat16* sWlo = sWhi + 128 * WS;
    __nv_bfloat16* sXhi = sWlo + 128 * WS;               // [64 e][XS k]
    __nv_bfloat16* sXlo = sXhi + TILE_E * XS;
    float* b1s   = (float*)(sXlo + TILE_E * XS);         // [128]
    float* w2s   = b1s + 128;                            // [128]
    float* Hpart = w2s + 128;                            // [64][4]
    int*   sidx  = (int*)(Hpart + TILE_E * 4);           // [64]
    int*   didx  = sidx + TILE_E;                        // [64]

    const int tid  = threadIdx.x;
    const int lane = tid & 31;
    const int warp = tid >> 5;
    const int wr   = warp >> 2;           // warp-row: edges [16*wr, 16*wr+16)
    const int wc   = warp & 3;            // warp-col: cols  [32*wc, 32*wc+32)
    const int g    = lane >> 2;           // 0..7
    const int q    = lane & 3;            // 0..3

    // ---- one-time per block: stage W1 as transposed bf16 hi/lo, b1/W2 to smem ----
    for (int i = tid; i < K2 * D; i += NTHREADS) {
        int k = i >> 7;                   // 0..255  (coalesced global read)
        int n = i & 127;                  // 0..127
        float w  = W1[i];
        __nv_bfloat16 h = __float2bfloat16(w);
        __nv_bfloat16 l = __float2bfloat16(w - __bfloat162float(h));
        sWhi[n * WS + k] = h;
        sWlo[n * WS + k] = l;
    }
    if (tid < 128) { b1s[tid] = b1[tid]; w2s[tid] = W2[tid]; }
    const float b2v = b2[0];
    __syncthreads();

    for (int tile = blockIdx.x; tile < n_tiles; tile += gridDim.x) {
        const int e0 = tile * TILE_E;

        // ---- edge indices ----
        if (tid < TILE_E) {
            int e = e0 + tid;
            sidx[tid] = (e < n_edges) ? eidx[e] : 0;
            didx[tid] = (e < n_edges) ? eidx[n_edges + e] : 0;
        }
        __syncthreads();

        // ---- gather + split: 8 threads per edge ----
        {
            const int el = tid >> 3;
            const int gg = tid & 7;
            const float4* srow = (const float4*)(src_emb + (size_t)sidx[el] * D);
            const float4* drow = (const float4*)(dst_emb + (size_t)didx[el] * D);
            __nv_bfloat16* xh = sXhi + el * XS;
            __nv_bfloat16* xl = sXlo + el * XS;
            #pragma unroll
            for (int i = 0; i < 4; ++i) {
                int c0 = (gg + 8 * i) * 4;
                float4 v = srow[gg + 8 * i];
                __nv_bfloat16 hx = __float2bfloat16(v.x), hy = __float2bfloat16(v.y);
                __nv_bfloat16 hz = __float2bfloat16(v.z), hw = __float2bfloat16(v.w);
                *(__nv_bfloat162*)(xh + c0)     = __nv_bfloat162(hx, hy);
                *(__nv_bfloat162*)(xh + c0 + 2) = __nv_bfloat162(hz, hw);
                *(__nv_bfloat162*)(xl + c0)     = __nv_bfloat162(
                    __float2bfloat16(v.x - __bfloat162float(hx)),
                    __float2bfloat16(v.y - __bfloat162float(hy)));
                *(__nv_bfloat162*)(xl + c0 + 2) = __nv_bfloat162(
                    __float2bfloat16(v.z - __bfloat162float(hz)),
                    __float2bfloat16(v.w - __bfloat162float(hw)));
                v = drow[gg + 8 * i];
                hx = __float2bfloat16(v.x); hy = __float2bfloat16(v.y);
                hz = __float2bfloat16(v.z); hw = __float2bfloat16(v.w);
                *(__nv_bfloat162*)(xh + c0 + D)     = __nv_bfloat162(hx, hy);
                *(__nv_bfloat162*)(xh + c0 + D + 2) = __nv_bfloat162(hz, hw);
                *(__nv_bfloat162*)(xl + c0 + D)     = __nv_bfloat162(
                    __float2bfloat16(v.x - __bfloat162float(hx)),
                    __float2bfloat16(v.y - __bfloat162float(hy)));
                *(__nv_bfloat162*)(xl + c0 + D + 2) = __nv_bfloat162(
                    __float2bfloat16(v.z - __bfloat162float(hz)),
                    __float2bfloat16(v.w - __bfloat162float(hw)));
            }
        }
        __syncthreads();

        // ---- tensor-core GEMM: warp tile 16 edges x 32 cols, K=256 ----
        float c[4][4];
        #pragma unroll
        for (int j = 0; j < 4; ++j)
            #pragma unroll
            for (int r = 0; r < 4; ++r) c[j][r] = 0.f;

        const __nv_bfloat16* aHi = sXhi + (wr * 16 + g) * XS + q * 2;
        const __nv_bfloat16* aLo = sXlo + (wr * 16 + g) * XS + q * 2;
        const __nv_bfloat16* bHi = sWhi + (wc * 32 + g) * WS + q * 2;
        const __nv_bfloat16* bLo = sWlo + (wc * 32 + g) * WS + q * 2;

        #pragma unroll 4
        for (int ks = 0; ks < K2 / 16; ++ks) {
            const int k0 = ks * 16;
            uint32_t ah0 = lds32(aHi + k0);
            uint32_t ah1 = lds32(aHi + 8 * XS + k0);
            uint32_t ah2 = lds32(aHi + k0 + 8);
            uint32_t ah3 = lds32(aHi + 8 * XS + k0 + 8);
            uint32_t al0 = lds32(aLo + k0);
            uint32_t al1 = lds32(aLo + 8 * XS + k0);
            uint32_t al2 = lds32(aLo + k0 + 8);
            uint32_t al3 = lds32(aLo + 8 * XS + k0 + 8);
            #pragma unroll
            for (int j = 0; j < 4; ++j) {
                const __nv_bfloat16* bh = bHi + j * 8 * WS + k0;
                const __nv_bfloat16* bl = bLo + j * 8 * WS + k0;
                uint32_t bh0 = lds32(bh), bh1 = lds32(bh + 8);
                uint32_t bl0 = lds32(bl), bl1 = lds32(bl + 8);
                mma16816(c[j], ah0, ah1, ah2, ah3, bh0, bh1);
                mma16816(c[j], ah0, ah1, ah2, ah3, bl0, bl1);
                mma16816(c[j], al0, al1, al2, al3, bh0, bh1);
            }
        }

        // ---- epilogue: relu + W2 dot over this warp's 32 cols ----
        float p0 = 0.f, p1 = 0.f;
        #pragma unroll
        for (int j = 0; j < 4; ++j) {
            int col = wc * 32 + j * 8 + q * 2;
            float ba = b1s[col], bb = b1s[col + 1];
            float wa = w2s[col], wb = w2s[col + 1];
            float h0 = c[j][0] + ba; h0 = h0 > 0.f ? h0 : 0.f;
            float h1 = c[j][1] + bb; h1 = h1 > 0.f ? h1 : 0.f;
            float h2 = c[j][2] + ba; h2 = h2 > 0.f ? h2 : 0.f;
            float h3 = c[j][3] + bb; h3 = h3 > 0.f ? h3 : 0.f;
            p0 = fmaf(h0, wa, fmaf(h1, wb, p0));
            p1 = fmaf(h2, wa, fmaf(h3, wb, p1));
        }
        p0 += __shfl_xor_sync(0xffffffffu, p0, 1);
        p0 += __shfl_xor_sync(0xffffffffu, p0, 2);
        p1 += __shfl_xor_sync(0xffffffffu, p1, 1);
        p1 += __shfl_xor_sync(0xffffffffu, p1, 2);
        if (q == 0) {
            Hpart[(wr * 16 + g) * 4 + wc]     = p0;
            Hpart[(wr * 16 + g + 8) * 4 + wc] = p1;
        }
        __syncthreads();

        if (tid < TILE_E) {
            int e = e0 + tid;
            if (e < n_edges) {
                float s = Hpart[tid * 4 + 0] + Hpart[tid * 4 + 1]
                        + Hpart[tid * 4 + 2] + Hpart[tid * 4 + 3] + b2v;
                out[e] = 1.f / (1.f + expf(-s));
            }
        }
        __syncthreads();   // Hpart/sX/sidx safe to overwrite next iteration
    }
}

extern "C" void kernel_launch(void* const* d_in, const int* in_sizes, int n_in,
                              void* d_out, int out_size)
{
    const float* src = (const float*)d_in[0];
    const float* dst = (const float*)d_in[1];
    const int*   ei  = (const int*)d_in[2];
    const float* W1  = (const float*)d_in[3];
    const float* b1  = (const float*)d_in[4];
    const float* W2  = (const float*)d_in[5];
    const float* b2  = (const float*)d_in[6];
    float*       out = (float*)d_out;

    const int n_edges = in_sizes[2] / 2;
    const int n_tiles = (n_edges + TILE_E - 1) / TILE_E;

    const int smem_bytes =
        (2 * 128 * WS + 2 * TILE_E * XS) * (int)sizeof(__nv_bfloat16)
        + (128 + 128 + TILE_E * 4) * (int)sizeof(float)
        + 2 * TILE_E * (int)sizeof(int);

    cudaFuncSetAttribute(edge_decoder_tc,
                         cudaFuncAttributeMaxDynamicSharedMemorySize, smem_bytes);

    int grid = GRID < n_tiles ? GRID : n_tiles;
    edge_decoder_tc<<<grid, NTHREADS, smem_bytes>>>(
        src, dst, ei, W1, b1, W2, b2, out, n_edges, n_tiles);
}

// round 6
// speedup vs baseline: 2.4976x; 1.0519x over previous
#include <cuda_runtime.h>
#include <cuda_bf16.h>
#include <cstdint>

// EdgeDecoder: out[e] = sigmoid( relu([src_e ; dst_e] @ W1 + b1) @ W2 + b2 )
// mma.sync bf16 hi/lo split (3 passes, fp32 accum) + ldmatrix fragment loads.
// Inputs: src f32[100000*128], dst f32[100000*128], edge_index i32[2*600000],
//         W1 f32[256*128], b1 f32[128], W2 f32[128], b2 f32[1]. Output f32[600000].

#define D        128
#define K2       256
#define TILE_E   64
#define NTHREADS 512            // 16 warps: 2 warp-rows (32 edges) x 8 warp-cols (16 cols)
#define XS       264            // bf16 row stride (256+8) -> LDSM conflict-free
#define WS       264
#define GRID     148

__device__ __forceinline__ uint32_t smem_u32(const void* p) {
    uint32_t a;
    asm("{ .reg .u64 t; cvta.to.shared.u64 t, %1; cvt.u32.u64 %0, t; }" : "=r"(a) : "l"(p));
    return a;
}

__device__ __forceinline__ void ldsm_x4(uint32_t& r0, uint32_t& r1,
                                        uint32_t& r2, uint32_t& r3, uint32_t addr) {
    asm volatile("ldmatrix.sync.aligned.m8n8.x4.shared.b16 {%0,%1,%2,%3}, [%4];"
                 : "=r"(r0), "=r"(r1), "=r"(r2), "=r"(r3) : "r"(addr));
}

__device__ __forceinline__ void mma16816(float c[4], uint32_t a0, uint32_t a1,
                                         uint32_t a2, uint32_t a3,
                                         uint32_t b0, uint32_t b1) {
    asm volatile(
        "mma.sync.aligned.m16n8k16.row.col.f32.bf16.bf16.f32 "
        "{%0,%1,%2,%3}, {%4,%5,%6,%7}, {%8,%9}, {%0,%1,%2,%3};\n"
        : "+f"(c[0]), "+f"(c[1]), "+f"(c[2]), "+f"(c[3])
        : "r"(a0), "r"(a1), "r"(a2), "r"(a3), "r"(b0), "r"(b1));
}

__global__ __launch_bounds__(NTHREADS, 1)
void edge_decoder_tc(const float* __restrict__ src_emb,
                     const float* __restrict__ dst_emb,
                     const int* __restrict__ eidx,
                     const float* __restrict__ W1,
                     const float* __restrict__ b1,
                     const float* __restrict__ W2,
                     const float* __restrict__ b2,
                     float* __restrict__ out,
                     int n_edges, int n_tiles)
{
    extern __shared__ char smem[];
    __nv_bfloat16* sWhi = (__nv_bfloat16*)smem;          // [128 n][WS k]
    __nv_bfloat16* sWlo = sWhi + 128 * WS;
    __nv_bfloat16* sXhi = sWlo + 128 * WS;               // [64 e][XS k]
    __nv_bfloat16* sXlo = sXhi + TILE_E * XS;
    float* b1s   = (float*)(sXlo + TILE_E * XS);         // [128]
    float* w2s   = b1s + 128;                            // [128]
    float* Hpart = w2s + 128;                            // [64][8]
    int*   sidx  = (int*)(Hpart + TILE_E * 8);           // [64]
    int*   didx  = sidx + TILE_E;                        // [64]

    const int tid  = threadIdx.x;
    const int lane = tid & 31;
    const int warp = tid >> 5;
    const int wr   = warp >> 3;           // 0..1 : edges [32*wr, 32*wr+32)
    const int wc   = warp & 7;            // 0..7 : cols  [16*wc, 16*wc+16)
    const int qr   = lane & 7;            // row within 8x8 matrix
    const int quad = lane >> 3;           // which of 4 matrices this lane addresses

    // ---- stage W1 as transposed bf16 hi/lo; b1/W2 to smem (once per block) ----
    for (int i = tid; i < K2 * D; i += NTHREADS) {
        int k = i >> 7;                   // coalesced global read of W1[k][n]
        int n = i & 127;
        float w  = W1[i];
        __nv_bfloat16 h = __float2bfloat16(w);
        __nv_bfloat16 l = __float2bfloat16(w - __bfloat162float(h));
        sWhi[n * WS + k] = h;
        sWlo[n * WS + k] = l;
    }
    if (tid < 128) { b1s[tid] = b1[tid]; w2s[tid] = W2[tid]; }
    const float b2v = b2[0];
    __syncthreads();

    // ---- per-lane ldmatrix base addresses (byte offsets into smem) ----
    // A x4 matrix order: (m0..7,k0) (m8..15,k0) (m0..7,k8) (m8..15,k8)
    const int arow = wr * 32 + (quad & 1) * 8 + qr;
    const int acol = (quad >> 1) * 8;
    const uint32_t aHi0 = smem_u32(sXhi) + (uint32_t)(arow * XS + acol) * 2;
    const uint32_t aLo0 = smem_u32(sXlo) + (uint32_t)(arow * XS + acol) * 2;
    const uint32_t aStepM = 16u * XS * 2;     // +16 edges (second m-tile)
    // B x4 matrix order: (n0..7,k0) (n0..7,k8) (n8..15,k0) (n8..15,k8)
    const int brow = wc * 16 + (quad >> 1) * 8 + qr;
    const int bcol = (quad & 1) * 8;
    const uint32_t bHi0 = smem_u32(sWhi) + (uint32_t)(brow * WS + bcol) * 2;
    const uint32_t bLo0 = smem_u32(sWlo) + (uint32_t)(brow * WS + bcol) * 2;

    for (int tile = blockIdx.x; tile < n_tiles; tile += gridDim.x) {
        const int e0 = tile * TILE_E;

        // ---- edge indices ----
        if (tid < TILE_E) {
            int e = e0 + tid;
            sidx[tid] = (e < n_edges) ? eidx[e] : 0;
            didx[tid] = (e < n_edges) ? eidx[n_edges + e] : 0;
        }
        __syncthreads();

        // ---- gather + hi/lo split: 8 threads per edge ----
        {
            const int el = tid >> 3;
            const int gg = tid & 7;
            const float4* srow = (const float4*)(src_emb + (size_t)sidx[el] * D);
            const float4* drow = (const float4*)(dst_emb + (size_t)didx[el] * D);
            __nv_bfloat16* xh = sXhi + el * XS;
            __nv_bfloat16* xl = sXlo + el * XS;
            #pragma unroll
            for (int i = 0; i < 4; ++i) {
                int c0 = (gg + 8 * i) * 4;
                float4 v = srow[gg + 8 * i];
                __nv_bfloat16 hx = __float2bfloat16(v.x), hy = __float2bfloat16(v.y);
                __nv_bfloat16 hz = __float2bfloat16(v.z), hw = __float2bfloat16(v.w);
                *(__nv_bfloat162*)(xh + c0)     = __nv_bfloat162(hx, hy);
                *(__nv_bfloat162*)(xh + c0 + 2) = __nv_bfloat162(hz, hw);
                *(__nv_bfloat162*)(xl + c0)     = __nv_bfloat162(
                    __float2bfloat16(v.x - __bfloat162float(hx)),
                    __float2bfloat16(v.y - __bfloat162float(hy)));
                *(__nv_bfloat162*)(xl + c0 + 2) = __nv_bfloat162(
                    __float2bfloat16(v.z - __bfloat162float(hz)),
                    __float2bfloat16(v.w - __bfloat162float(hw)));
                v = drow[gg + 8 * i];
                hx = __float2bfloat16(v.x); hy = __float2bfloat16(v.y);
                hz = __float2bfloat16(v.z); hw = __float2bfloat16(v.w);
                *(__nv_bfloat162*)(xh + c0 + D)     = __nv_bfloat162(hx, hy);
                *(__nv_bfloat162*)(xh + c0 + D + 2) = __nv_bfloat162(hz, hw);
                *(__nv_bfloat162*)(xl + c0 + D)     = __nv_bfloat162(
                    __float2bfloat16(v.x - __bfloat162float(hx)),
                    __float2bfloat16(v.y - __bfloat162float(hy)));
                *(__nv_bfloat162*)(xl + c0 + D + 2) = __nv_bfloat162(
                    __float2bfloat16(v.z - __bfloat162float(hz)),
                    __float2bfloat16(v.w - __bfloat162float(hw)));
            }
        }
        __syncthreads();

        // ---- tensor cores: warp tile 32 edges x 16 cols, K=256 ----
        float c[2][2][4];
        #pragma unroll
        for (int mt = 0; mt < 2; ++mt)
            #pragma unroll
            for (int nt = 0; nt < 2; ++nt)
                #pragma unroll
                for (int r = 0; r < 4; ++r) c[mt][nt][r] = 0.f;

        #pragma unroll 4
        for (int ks = 0; ks < K2 / 16; ++ks) {
            const uint32_t off = (uint32_t)ks * 32;   // k0*2 bytes
            uint32_t ah[8], al[8], bh[4], bl[4];
            ldsm_x4(ah[0], ah[1], ah[2], ah[3], aHi0 + off);
            ldsm_x4(ah[4], ah[5], ah[6], ah[7], aHi0 + aStepM + off);
            ldsm_x4(al[0], al[1], al[2], al[3], aLo0 + off);
            ldsm_x4(al[4], al[5], al[6], al[7], aLo0 + aStepM + off);
            ldsm_x4(bh[0], bh[1], bh[2], bh[3], bHi0 + off);
            ldsm_x4(bl[0], bl[1], bl[2], bl[3], bLo0 + off);
            #pragma unroll
            for (int mt = 0; mt < 2; ++mt) {
                #pragma unroll
                for (int nt = 0; nt < 2; ++nt) {
                    mma16816(c[mt][nt], ah[mt*4+0], ah[mt*4+1], ah[mt*4+2], ah[mt*4+3],
                             bh[nt*2], bh[nt*2+1]);
                    mma16816(c[mt][nt], ah[mt*4+0], ah[mt*4+1], ah[mt*4+2], ah[mt*4+3],
                             bl[nt*2], bl[nt*2+1]);
                    mma16816(c[mt][nt], al[mt*4+0], al[mt*4+1], al[mt*4+2], al[mt*4+3],
                             bh[nt*2], bh[nt*2+1]);
                }
            }
        }

        // ---- epilogue: relu + W2 dot over this warp's 16 cols ----
        // c[mt][nt]: rows (wr*32 + mt*16 + t/4, +8); cols (wc*16 + nt*8 + 2*(t%4), +1)
        {
            const int tq = lane >> 2;     // 0..7
            const int tk = lane & 3;      // 0..3
            float p[4];                   // rows: mt*16 + {tq, tq+8}
            #pragma unroll
            for (int mt = 0; mt < 2; ++mt) {
                float s0 = 0.f, s1 = 0.f;
                #pragma unroll
                for (int nt = 0; nt < 2; ++nt) {
                    int col = wc * 16 + nt * 8 + tk * 2;
                    float ba = b1s[col], bb = b1s[col + 1];
                    float wa = w2s[col], wb = w2s[col + 1];
                    float h;
                    h = c[mt][nt][0] + ba; h = h > 0.f ? h : 0.f; s0 = fmaf(h, wa, s0);
                    h = c[mt][nt][1] + bb; h = h > 0.f ? h : 0.f; s0 = fmaf(h, wb, s0);
                    h = c[mt][nt][2] + ba; h = h > 0.f ? h : 0.f; s1 = fmaf(h, wa, s1);
                    h = c[mt][nt][3] + bb; h = h > 0.f ? h : 0.f; s1 = fmaf(h, wb, s1);
                }
                p[mt * 2]     = s0;
                p[mt * 2 + 1] = s1;
            }
            #pragma unroll
            for (int i = 0; i < 4; ++i) {
                p[i] += __shfl_xor_sync(0xffffffffu, p[i], 1);
                p[i] += __shfl_xor_sync(0xffffffffu, p[i], 2);
            }
            if (tk == 0) {
                int rbase = wr * 32;
                Hpart[(rbase + tq)      * 8 + wc] = p[0];
                Hpart[(rbase + tq + 8)  * 8 + wc] = p[1];
                Hpart[(rbase + tq + 16) * 8 + wc] = p[2];
                Hpart[(rbase + tq + 24) * 8 + wc] = p[3];
            }
        }
        __syncthreads();

        if (tid < TILE_E) {
            int e = e0 + tid;
            if (e < n_edges) {
                const float* hp = Hpart + tid * 8;
                float s = ((hp[0] + hp[1]) + (hp[2] + hp[3]))
                        + ((hp[4] + hp[5]) + (hp[6] + hp[7])) + b2v;
                out[e] = 1.f / (1.f + expf(-s));
            }
        }
        __syncthreads();   // Hpart/sX/sidx safe to overwrite next iteration
    }
}

extern "C" void kernel_launch(void* const* d_in, const int* in_sizes, int n_in,
                              void* d_out, int out_size)
{
    const float* src = (const float*)d_in[0];
    const float* dst = (const float*)d_in[1];
    const int*   ei  = (const int*)d_in[2];
    const float* W1  = (const float*)d_in[3];
    const float* b1  = (const float*)d_in[4];
    const float* W2  = (const float*)d_in[5];
    const float* b2  = (const float*)d_in[6];
    float*       out = (float*)d_out;

    const int n_edges = in_sizes[2] / 2;
    const int n_tiles = (n_edges + TILE_E - 1) / TILE_E;

    const int smem_bytes =
        (2 * 128 * WS + 2 * TILE_E * XS) * (int)sizeof(__nv_bfloat16)
        + (128 + 128 + TILE_E * 8) * (int)sizeof(float)
        + 2 * TILE_E * (int)sizeof(int);

    cudaFuncSetAttribute(edge_decoder_tc,
                         cudaFuncAttributeMaxDynamicSharedMemorySize, smem_bytes);

    int grid = GRID < n_tiles ? GRID : n_tiles;
    edge_decoder_tc<<<grid, NTHREADS, smem_bytes>>>(
        src, dst, ei, W1, b1, W2, b2, out, n_edges, n_tiles);
}

// round 7
// speedup vs baseline: 2.6217x; 1.0497x over previous
#include <cuda_runtime.h>
#include <cuda_bf16.h>
#include <cstdint>

// EdgeDecoder: out[e] = sigmoid( relu([src_e ; dst_e] @ W1 + b1) @ W2 + b2 )
// Round 7: prepass converts node tables to bf16 hi/lo; main kernel uses
// cp.async double-buffered gather + 32x32 warp-tile mma.sync (8 MMA warps).

#define D        128
#define K2       256
#define TILE_E   64
#define NTHREADS 512
#define GRID     148
#define N_NODES_MAX 100000

// SMEM layout (bytes)
#define WSTRIDE  264                           // W row stride in elems (528B)
#define XSTRIDE  136                           // X half-buf row stride in elems (272B)
#define OFF_WHI  0                             // [128 n][264 k] bf16 = 67584
#define OFF_WLO  67584
#define OFF_X0   135168                        // half-buf 0: hi 64x272B, lo 64x272B
#define XBUF_SZ  34816
#define OFF_X1   (OFF_X0 + XBUF_SZ)
#define OFF_B1   (OFF_X1 + XBUF_SZ)            // 204800 f32[128]
#define OFF_W2   (OFF_B1 + 512)
#define OFF_HP   (OFF_W2 + 512)                // f32[64][4]
#define SMEM_TOTAL (OFF_HP + 1024)             // 206848

// Pre-converted node tables: [node][hi 128 bf16 | lo 128 bf16] = 512B/node
__device__ __align__(16) __nv_bfloat16 g_src_bf[(size_t)N_NODES_MAX * 256];
__device__ __align__(16) __nv_bfloat16 g_dst_bf[(size_t)N_NODES_MAX * 256];

__device__ __forceinline__ uint32_t smem_u32(const void* p) {
    uint32_t a;
    asm("{ .reg .u64 t; cvta.to.shared.u64 t, %1; cvt.u32.u64 %0, t; }" : "=r"(a) : "l"(p));
    return a;
}
__device__ __forceinline__ void cp16(uint32_t saddr, const void* gaddr) {
    asm volatile("cp.async.cg.shared.global [%0], [%1], 16;" :: "r"(saddr), "l"(gaddr));
}
#define CP_COMMIT() asm volatile("cp.async.commit_group;" ::: "memory")
#define CP_WAIT1()  asm volatile("cp.async.wait_group 1;" ::: "memory")

__device__ __forceinline__ void ldsm_x4(uint32_t& r0, uint32_t& r1,
                                        uint32_t& r2, uint32_t& r3, uint32_t addr) {
    asm volatile("ldmatrix.sync.aligned.m8n8.x4.shared.b16 {%0,%1,%2,%3}, [%4];"
                 : "=r"(r0), "=r"(r1), "=r"(r2), "=r"(r3) : "r"(addr));
}
__device__ __forceinline__ void mma16816(float c[4], const uint32_t a[4],
                                         uint32_t b0, uint32_t b1) {
    asm volatile(
        "mma.sync.aligned.m16n8k16.row.col.f32.bf16.bf16.f32 "
        "{%0,%1,%2,%3}, {%4,%5,%6,%7}, {%8,%9}, {%0,%1,%2,%3};\n"
        : "+f"(c[0]), "+f"(c[1]), "+f"(c[2]), "+f"(c[3])
        : "r"(a[0]), "r"(a[1]), "r"(a[2]), "r"(a[3]), "r"(b0), "r"(b1));
}

// ---------------- prepass: fp32 tables -> bf16 hi/lo tables ----------------
__global__ void convert_tables(const float* __restrict__ src,
                               const float* __restrict__ dst, int n_nodes)
{
    const int per_tab = n_nodes * 32;     // float4 per table
    for (int v = blockIdx.x * blockDim.x + threadIdx.x; v < 2 * per_tab;
         v += gridDim.x * blockDim.x) {
        const float4* tab = (const float4*)(v < per_tab ? src : dst);
        __nv_bfloat16* ot = (v < per_tab) ? g_src_bf : g_dst_bf;
        int u = (v < per_tab) ? v : v - per_tab;
        int node = u >> 5, q = u & 31;
        float4 x = tab[u];
        __nv_bfloat16 hx = __float2bfloat16(x.x), hy = __float2bfloat16(x.y);
        __nv_bfloat16 hz = __float2bfloat16(x.z), hw = __float2bfloat16(x.w);
        __nv_bfloat162* oh = (__nv_bfloat162*)(ot + (size_t)node * 256 + q * 4);
        __nv_bfloat162* ol = (__nv_bfloat162*)(ot + (size_t)node * 256 + 128 + q * 4);
        oh[0] = __nv_bfloat162(hx, hy);
        oh[1] = __nv_bfloat162(hz, hw);
        ol[0] = __nv_bfloat162(__float2bfloat16(x.x - __bfloat162float(hx)),
                               __float2bfloat16(x.y - __bfloat162float(hy)));
        ol[1] = __nv_bfloat162(__float2bfloat16(x.z - __bfloat162float(hz)),
                               __float2bfloat16(x.w - __bfloat162float(hw)));
    }
}

// ---------------- main kernel ----------------
__global__ __launch_bounds__(NTHREADS, 1)
void edge_decoder_tc(const int* __restrict__ eidx,
                     const float* __restrict__ W1,
                     const float* __restrict__ b1,
                     const float* __restrict__ W2,
                     const float* __restrict__ b2,
                     float* __restrict__ out,
                     int n_edges, int n_tiles)
{
    extern __shared__ char smem[];
    const uint32_t sb = smem_u32(smem);
    const int tid  = threadIdx.x;
    const int lane = tid & 31;
    const int warp = tid >> 5;

    float* b1s   = (float*)(smem + OFF_B1);
    float* w2s   = (float*)(smem + OFF_W2);
    float* Hpart = (float*)(smem + OFF_HP);

    // gather mapping: 8 threads per edge row
    const int gel = tid >> 3;             // 0..63
    const int gc  = tid & 7;              // 0..7

    // issue cp.async for (tile, half) into half-buffer hb
    auto issue_half = [&](int tile, int half, int hb) {
        if (tile < n_tiles) {
            int e = tile * TILE_E + gel;
            int idx = (e < n_edges) ? eidx[(half ? n_edges : 0) + e] : 0;
            const char* g = (const char*)(half ? g_dst_bf : g_src_bf) + (size_t)idx * 512;
            uint32_t dhi = sb + (hb ? OFF_X1 : OFF_X0) + (uint32_t)gel * 272;
            uint32_t dlo = dhi + 64u * 272;
            cp16(dhi + gc * 16,        g + gc * 16);
            cp16(dhi + (gc + 8) * 16,  g + (gc + 8) * 16);
            cp16(dlo + gc * 16,        g + 256 + gc * 16);
            cp16(dlo + (gc + 8) * 16,  g + 256 + (gc + 8) * 16);
        }
        CP_COMMIT();
    };

    // prologue: start the first gather before W staging (overlaps)
    int tile = blockIdx.x;
    issue_half(tile, 0, 0);

    // one-time: W1 -> transposed bf16 hi/lo; b1/W2
    {
        __nv_bfloat16* wh = (__nv_bfloat16*)(smem + OFF_WHI);
        __nv_bfloat16* wl = (__nv_bfloat16*)(smem + OFF_WLO);
        for (int i = tid; i < K2 * D; i += NTHREADS) {
            int k = i >> 7;
            int n = i & 127;
            float w = W1[i];
            __nv_bfloat16 h = __float2bfloat16(w);
            wh[n * WSTRIDE + k] = h;
            wl[n * WSTRIDE + k] = __float2bfloat16(w - __bfloat162float(h));
        }
        if (tid < 128) { b1s[tid] = b1[tid]; w2s[tid] = W2[tid]; }
    }
    const float b2v = b2[0];
    __syncthreads();

    // MMA warp geometry: warps 0..7: 2 warp-rows (32 edges) x 4 warp-cols (32 cols)
    const int wr = (warp >> 2) & 1;
    const int wc = warp & 3;
    const int quad = lane >> 3, qr = lane & 7;
    // A frag lane addressing (within half-buffer, stride 272B)
    const uint32_t aOff = (uint32_t)((wr * 32 + (quad & 1) * 8 + qr) * 272
                                     + (quad >> 1) * 16);     // elem col *2B
    // B frag lane addressing (W tiles, stride 528B)
    const uint32_t bRowOff = (uint32_t)((wc * 32 + (quad >> 1) * 8 + qr) * 528
                                        + (quad & 1) * 16);
    const uint32_t bHiBase = sb + OFF_WHI + bRowOff;
    const uint32_t bLoBase = sb + OFF_WLO + bRowOff;

    for (; tile < n_tiles; tile += gridDim.x) {
        float c[2][4][4];
        #pragma unroll
        for (int mt = 0; mt < 2; ++mt)
            #pragma unroll
            for (int nt = 0; nt < 4; ++nt)
                #pragma unroll
                for (int r = 0; r < 4; ++r) c[mt][nt][r] = 0.f;

        #pragma unroll
        for (int h = 0; h < 2; ++h) {
            // start next half's gather into the other buffer
            if (h == 0) issue_half(tile, 1, 1);
            else        issue_half(tile + gridDim.x, 0, 0);

            CP_WAIT1();           // current half's data complete
            __syncthreads();      // visible to all warps

            if (warp < 8) {
                const uint32_t aHi = sb + (h ? OFF_X1 : OFF_X0) + aOff;
                const uint32_t aLo = aHi + 64u * 272;
                const uint32_t bK  = (uint32_t)h * 256;   // W k offset bytes
                #pragma unroll 4
                for (int ks = 0; ks < 8; ++ks) {
                    const uint32_t ko = (uint32_t)ks * 32;
                    uint32_t ah[8], al[8], bh[8], bl[8];
                    ldsm_x4(ah[0], ah[1], ah[2], ah[3], aHi + ko);
                    ldsm_x4(ah[4], ah[5], ah[6], ah[7], aHi + 4352 + ko);
                    ldsm_x4(al[0], al[1], al[2], al[3], aLo + ko);
                    ldsm_x4(al[4], al[5], al[6], al[7], aLo + 4352 + ko);
                    ldsm_x4(bh[0], bh[1], bh[2], bh[3], bHiBase + bK + ko);
                    ldsm_x4(bh[4], bh[5], bh[6], bh[7], bHiBase + 8448 + bK + ko);
                    ldsm_x4(bl[0], bl[1], bl[2], bl[3], bLoBase + bK + ko);
                    ldsm_x4(bl[4], bl[5], bl[6], bl[7], bLoBase + 8448 + bK + ko);
                    #pragma unroll
                    for (int mt = 0; mt < 2; ++mt) {
                        #pragma unroll
                        for (int nt = 0; nt < 4; ++nt) {
                            mma16816(c[mt][nt], ah + mt * 4, bh[nt * 2], bh[nt * 2 + 1]);
                            mma16816(c[mt][nt], ah + mt * 4, bl[nt * 2], bl[nt * 2 + 1]);
                            mma16816(c[mt][nt], al + mt * 4, bh[nt * 2], bh[nt * 2 + 1]);
                        }
                    }
                }
            }
            __syncthreads();      // all reads of this half-buffer done
        }

        // ---- epilogue (MMA warps): relu + W2 dot over this warp's 32 cols ----
        if (warp < 8) {
            const int tq = lane >> 2;     // 0..7
            const int tk = lane & 3;      // 0..3
            float p[4];
            #pragma unroll
            for (int mt = 0; mt < 2; ++mt) {
                float s0 = 0.f, s1 = 0.f;
                #pragma unroll
                for (int nt = 0; nt < 4; ++nt) {
                    int col = wc * 32 + nt * 8 + tk * 2;
                    float ba = b1s[col], bb = b1s[col + 1];
                    float wa = w2s[col], wb = w2s[col + 1];
                    float h;
                    h = c[mt][nt][0] + ba; h = h > 0.f ? h : 0.f; s0 = fmaf(h, wa, s0);
                    h = c[mt][nt][1] + bb; h = h > 0.f ? h : 0.f; s0 = fmaf(h, wb, s0);
                    h = c[mt][nt][2] + ba; h = h > 0.f ? h : 0.f; s1 = fmaf(h, wa, s1);
                    h = c[mt][nt][3] + bb; h = h > 0.f ? h : 0.f; s1 = fmaf(h, wb, s1);
                }
                p[mt * 2]     = s0;
                p[mt * 2 + 1] = s1;
            }
            #pragma unroll
            for (int i = 0; i < 4; ++i) {
                p[i] += __shfl_xor_sync(0xffffffffu, p[i], 1);
                p[i] += __shfl_xor_sync(0xffffffffu, p[i], 2);
            }
            if (tk == 0) {
                int rb = wr * 32;
                Hpart[(rb + tq)      * 4 + wc] = p[0];
                Hpart[(rb + tq + 8)  * 4 + wc] = p[1];
                Hpart[(rb + tq + 16) * 4 + wc] = p[2];
                Hpart[(rb + tq + 24) * 4 + wc] = p[3];
            }
        }
        __syncthreads();

        if (tid < TILE_E) {
            int e = tile * TILE_E + tid;
            if (e < n_edges) {
                const float* hp = Hpart + tid * 4;
                float s = (hp[0] + hp[1]) + (hp[2] + hp[3]) + b2v;
                out[e] = 1.f / (1.f + expf(-s));
            }
        }
        __syncthreads();   // Hpart safe before next tile's epilogue
    }
}

extern "C" void kernel_launch(void* const* d_in, const int* in_sizes, int n_in,
                              void* d_out, int out_size)
{
    const float* src = (const float*)d_in[0];
    const float* dst = (const float*)d_in[1];
    const int*   ei  = (const int*)d_in[2];
    const float* W1  = (const float*)d_in[3];
    const float* b1  = (const float*)d_in[4];
    const float* W2  = (const float*)d_in[5];
    const float* b2  = (const float*)d_in[6];
    float*       out = (float*)d_out;

    const int n_nodes = in_sizes[0] / D;
    const int n_edges = in_sizes[2] / 2;
    const int n_tiles = (n_edges + TILE_E - 1) / TILE_E;

    convert_tables<<<1480, 256>>>(src, dst, n_nodes);

    cudaFuncSetAttribute(edge_decoder_tc,
                         cudaFuncAttributeMaxDynamicSharedMemorySize, SMEM_TOTAL);
    int grid = GRID < n_tiles ? GRID : n_tiles;
    edge_decoder_tc<<<grid, NTHREADS, SMEM_TOTAL>>>(
        ei, W1, b1, W2, b2, out, n_edges, n_tiles);
}